// round 3
// baseline (speedup 1.0000x reference)
#include <cuda_runtime.h>
#include <cstdint>

// Problem constants
#define T_STEPS 8192
#define D_INP   512
#define HDIM    768      // H
#define G3      2304     // 3*H
#define RTOT    4608     // 2 dirs * 3H
#define DH2     1536     // 2*H
#define NCTA    128      // persistent CTAs in the sequential pass
#define NWARP   12       // GRU units per CTA (one warp each); 128*12 = 1536 units

// ---------------- scratch (device globals; no allocation allowed) -------------
__device__ float g_Gi0[(size_t)T_STEPS * RTOT];        // W_ih0 @ x + b_ih0   [T,4608]
__device__ float g_Gi1[(size_t)T_STEPS * RTOT];        // W_ih1 @ h0seq + b   [T,4608]
__device__ float g_H0[(size_t)(T_STEPS + 1) * DH2];    // layer0 hidden seq (row 0 = init)
__device__ float g_H1[(size_t)(T_STEPS + 1) * DH2];    // layer1 hidden seq
__device__ unsigned g_cnt[2];
__device__ unsigned g_ep[2];

// ---------------- init: seed hidden states, reset barrier state ---------------
__global__ void init_kernel(const float* __restrict__ h0) {
    int j = blockIdx.x * blockDim.x + threadIdx.x;
    if (j < DH2) {
        // torch layout h0[L*2, H]; layer0 dirs = rows 0,1 ; layer1 dirs = rows 2,3
        g_H0[j] = h0[j];
        g_H1[j] = h0[DH2 + j];
    }
    if (j == 0) { g_cnt[0] = 0; g_cnt[1] = 0; g_ep[0] = 0; g_ep[1] = 0; }
}

// ---------------- SGEMM (NT): C[t][m] = sum_k A[t][k] * B[m][k] + bias[m] -----
// A: [T, K] row-major (lda = K), B: [RTOT, K] row-major, C: [T, RTOT]
// 128x128 tile, BK=16, 256 threads, 8x8 per-thread microtile.
__global__ __launch_bounds__(256) void sgemm_nt(
    const float* __restrict__ A, const float* __restrict__ B,
    const float* __restrict__ bias, int K, int which)
{
    float* C = which ? g_Gi1 : g_Gi0;
    const float* Ab;
    if (A == nullptr) Ab = g_H0 + DH2 + (size_t)blockIdx.y * 128 * K;   // layer-1 input seq
    else              Ab = A + (size_t)blockIdx.y * 128 * K;

    __shared__ float As[16][128];
    __shared__ float Bs[16][128];
    const int tid = threadIdx.x;
    const int tx = tid & 15;        // N (rows of W)
    const int ty = tid >> 4;        // M (timesteps)
    const float* Bb = B + (size_t)blockIdx.x * 128 * K;

    float acc[8][8];
#pragma unroll
    for (int i = 0; i < 8; i++)
#pragma unroll
        for (int j = 0; j < 8; j++) acc[i][j] = 0.f;

    for (int k0 = 0; k0 < K; k0 += 16) {
#pragma unroll
        for (int q = 0; q < 2; q++) {
            int f   = tid * 2 + q;          // 0..511 float4 slots
            int row = f >> 2;
            int c4  = (f & 3) * 4;
            float4 va = *reinterpret_cast<const float4*>(Ab + (size_t)row * K + k0 + c4);
            As[c4 + 0][row] = va.x; As[c4 + 1][row] = va.y;
            As[c4 + 2][row] = va.z; As[c4 + 3][row] = va.w;
            float4 vb = *reinterpret_cast<const float4*>(Bb + (size_t)row * K + k0 + c4);
            Bs[c4 + 0][row] = vb.x; Bs[c4 + 1][row] = vb.y;
            Bs[c4 + 2][row] = vb.z; Bs[c4 + 3][row] = vb.w;
        }
        __syncthreads();
#pragma unroll
        for (int kk = 0; kk < 16; kk++) {
            float4 a0 = *reinterpret_cast<const float4*>(&As[kk][ty * 8]);
            float4 a1 = *reinterpret_cast<const float4*>(&As[kk][ty * 8 + 4]);
            float4 b0 = *reinterpret_cast<const float4*>(&Bs[kk][tx * 8]);
            float4 b1 = *reinterpret_cast<const float4*>(&Bs[kk][tx * 8 + 4]);
            float ra[8] = {a0.x, a0.y, a0.z, a0.w, a1.x, a1.y, a1.z, a1.w};
            float rb[8] = {b0.x, b0.y, b0.z, b0.w, b1.x, b1.y, b1.z, b1.w};
#pragma unroll
            for (int i = 0; i < 8; i++)
#pragma unroll
                for (int j = 0; j < 8; j++)
                    acc[i][j] += ra[i] * rb[j];
        }
        __syncthreads();
    }
    const int cb = blockIdx.x * 128 + tx * 8;
    float bb[8];
#pragma unroll
    for (int j = 0; j < 8; j++) bb[j] = bias[cb + j];
#pragma unroll
    for (int i = 0; i < 8; i++) {
        float* Cp = C + (size_t)(blockIdx.y * 128 + ty * 8 + i) * RTOT + cb;
#pragma unroll
        for (int j = 0; j < 8; j++) Cp[j] = acc[i][j] + bb[j];
    }
}

// ---------------- sequential GRU pass (persistent, grid-barrier per step) -----
// One warp per GRU unit (dir d, hidden index i). w_hh rows live in registers
// (24 fp32 per gate per lane). Per step: broadcast h via L2, 3 dot products,
// warp reduce, gate math on lane 0, write 1 float, grid barrier.
__global__ __launch_bounds__(NWARP * 32) void gru_pass(
    const float* __restrict__ Whh,   // [2, 3H, H] flat
    const float* __restrict__ bhh,   // [2, 3H] flat
    int layer)
{
    const float* Gi = layer ? g_Gi1 : g_Gi0;
    float* Hs = layer ? g_H1 : g_H0;

    __shared__ float h_sh[DH2];
    const int warp = threadIdx.x >> 5;
    const int lane = threadIdx.x & 31;
    const int u = blockIdx.x * NWARP + warp;   // 0..1535
    const int d = u / HDIM;
    const int i = u % HDIM;

    // Load this unit's w_hh rows (r,z,n) into registers, strided by lane.
    float wr[24], wz[24], wn[24];
    const float* base = Whh + (size_t)d * G3 * HDIM;
#pragma unroll
    for (int m = 0; m < 24; m++) {
        int k = lane + 32 * m;
        wr[m] = base[(size_t)(i) * HDIM + k];
        wz[m] = base[(size_t)(HDIM + i) * HDIM + k];
        wn[m] = base[(size_t)(2 * HDIM + i) * HDIM + k];
    }
    const float br = bhh[d * G3 + i];
    const float bz = bhh[d * G3 + HDIM + i];
    const float bn = bhh[d * G3 + 2 * HDIM + i];

    volatile unsigned* ep = &g_ep[layer];

    for (int t = 0; t < T_STEPS; t++) {
        // Prefetch precomputed input-side gates early (no dependency on h).
        float gr = 0.f, gz = 0.f, gn = 0.f;
        if (lane == 0) {
            const float* gp = Gi + (size_t)t * RTOT + d * G3 + i;
            gr = __ldg(gp);
            gz = __ldg(gp + HDIM);
            gn = __ldg(gp + 2 * HDIM);
        }
        // Broadcast previous hidden state (written last step by other SMs -> L2).
        const float* hp = Hs + (size_t)t * DH2;
        for (int j = threadIdx.x; j < DH2; j += NWARP * 32) h_sh[j] = __ldcg(hp + j);
        __syncthreads();

        float ar = 0.f, az = 0.f, an = 0.f;
        const float* hb = h_sh + d * HDIM;
#pragma unroll
        for (int m = 0; m < 24; m++) {
            float hv = hb[lane + 32 * m];
            ar += wr[m] * hv;
            az += wz[m] * hv;
            an += wn[m] * hv;
        }
#pragma unroll
        for (int off = 16; off > 0; off >>= 1) {
            ar += __shfl_down_sync(0xffffffffu, ar, off);
            az += __shfl_down_sync(0xffffffffu, az, off);
            an += __shfl_down_sync(0xffffffffu, an, off);
        }
        if (lane == 0) {
            float r = 1.f / (1.f + __expf(-(gr + ar + br)));
            float z = 1.f / (1.f + __expf(-(gz + az + bz)));
            float n = tanhf(gn + r * (an + bn));
            float hprev = hb[i];
            Hs[(size_t)(t + 1) * DH2 + u] = (1.f - z) * n + z * hprev;
        }
        __syncthreads();
        // ---- grid barrier (monotone count + epoch flag) ----
        if (threadIdx.x == 0) {
            __threadfence();
            unsigned old = atomicAdd(&g_cnt[layer], 1u);
            if (old == (unsigned)(t + 1) * NCTA - 1u) {
                __threadfence();
                atomicExch(&g_ep[layer], (unsigned)(t + 1));
            }
            while (*ep < (unsigned)(t + 1)) { }
            __threadfence();
        }
        __syncthreads();
    }
}

// ---------------- final FC + sigmoid ------------------------------------------
__global__ void fc_kernel(const float* __restrict__ fcw,
                          const float* __restrict__ fcb,
                          float* __restrict__ out)
{
    int gw = (blockIdx.x * blockDim.x + threadIdx.x) >> 5;   // output index
    int lane = threadIdx.x & 31;
    if (gw >= 256) return;
    const float* h = g_H1 + (size_t)T_STEPS * DH2;
    float acc = 0.f;
    for (int k = lane; k < DH2; k += 32)
        acc += fcw[(size_t)gw * DH2 + k] * h[k];
#pragma unroll
    for (int off = 16; off > 0; off >>= 1)
        acc += __shfl_down_sync(0xffffffffu, acc, off);
    if (lane == 0)
        out[gw] = 1.f / (1.f + __expf(-(acc + fcb[gw])));
}

// ---------------- launch ------------------------------------------------------
extern "C" void kernel_launch(void* const* d_in, const int* in_sizes, int n_in,
                              void* d_out, int out_size)
{
    const float* x     = (const float*)d_in[0];
    const float* h0    = (const float*)d_in[1];
    const float* w_ih0 = (const float*)d_in[2];
    const float* w_hh0 = (const float*)d_in[3];
    const float* b_ih0 = (const float*)d_in[4];
    const float* b_hh0 = (const float*)d_in[5];
    const float* w_ih1 = (const float*)d_in[6];
    const float* w_hh1 = (const float*)d_in[7];
    const float* b_ih1 = (const float*)d_in[8];
    const float* b_hh1 = (const float*)d_in[9];
    const float* fc_w  = (const float*)d_in[10];
    const float* fc_b  = (const float*)d_in[11];
    float* out = (float*)d_out;

    (void)in_sizes; (void)n_in; (void)out_size;

    init_kernel<<<6, 256>>>(h0);

    // Gi0 = W_ih0 @ x + b_ih0
    sgemm_nt<<<dim3(RTOT / 128, T_STEPS / 128), 256>>>(x, w_ih0, b_ih0, D_INP, 0);

    // layer 0 sequential pass
    gru_pass<<<NCTA, NWARP * 32>>>(w_hh0, b_hh0, 0);

    // Gi1 = W_ih1 @ h0_seq + b_ih1  (A=nullptr -> kernel uses g_H0+DH2)
    sgemm_nt<<<dim3(RTOT / 128, T_STEPS / 128), 256>>>(nullptr, w_ih1, b_ih1, DH2, 1);

    // layer 1 sequential pass
    gru_pass<<<NCTA, NWARP * 32>>>(w_hh1, b_hh1, 1);

    // final FC + sigmoid
    fc_kernel<<<32, 256>>>(fc_w, fc_b, out);
}